// round 10
// baseline (speedup 1.0000x reference)
#include <cuda_runtime.h>
#include <cstdint>

// ---------------------------------------------------------------------------
// BLNN round 10: two independent 8-warp teams (4 rows each) per CTA.
//  - Teams share only read-only weights; all loop syncs are team-scoped
//    named barriers (bar.sync team+1, 256). Teams drift freely, so one
//    team's combine (L1 burst) overlaps the other's GEMV (fma) phase.
//  - Convergence: per-team u64 atomic {cnt<<52|err} posted at loop top
//    (err(it-1)); spin+flag check just BEFORE combine-D => ~full iteration
//    of slack hides atomic latency and cross-CTA spread.
//  - f32x2 FMA GEMVs; 4-row float4 activation broadcasts; f32x2 combines.
// ---------------------------------------------------------------------------

#define NCTA      128
#define THREADS   512
#define NUNITS    256ULL
#define MAX_IT    500
#define CNT_SHIFT 52
#define ERR_MASK  ((1ULL << 52) - 1)
#define ERR_THRESH 4398046511ULL   // 0.001*1024*2^32

typedef unsigned long long u64;

__device__ u64 g_stat[MAX_IT];

__global__ void blnn_init_kernel() {
    int i = blockIdx.x * blockDim.x + threadIdx.x;
    if (i < MAX_IT) g_stat[i] = 0ULL;
}

__device__ __forceinline__ u64 dup2(float w) {
    u64 r; asm("mov.b64 %0,{%1,%1};" : "=l"(r) : "f"(w)); return r;
}
__device__ __forceinline__ u64 fma2(u64 a, u64 b, u64 c) {
    u64 d; asm("fma.rn.f32x2 %0,%1,%2,%3;" : "=l"(d) : "l"(a), "l"(b), "l"(c));
    return d;
}
__device__ __forceinline__ float2 add2(float2 a, float2 b) {
    return make_float2(a.x + b.x, a.y + b.y);
}
__device__ __forceinline__ void act2(float a, float& sp, float& sg) {
    float e = __expf(-fabsf(a));
    float u = 1.0f + e;
    float r = __fdividef(1.0f, u);
    sp = fmaxf(a, 0.0f) + __logf(u);
    sg = (a >= 0.0f) ? r : e * r;
}

// ---- shared layout (float offsets) ----
#define OFF_WZ1T  0        // 16512
#define OFF_WY0T  16512    // 8256
#define OFF_WY1T  24768    // 8256
#define OFF_WY2V  33024    // 64
#define OFF_WZ2V  33088    // 128
#define OFF_BY0V  33216    // 128
#define OFF_BY1V  33344    // 128
#define OFF_MISC  33472    // 8  [0]=by2
#define OFF_TEAM  33480
#define TEAM_STRIDE 4224
// per-team offsets (floats)
#define T_X     0        // [c*4+r]      256
#define T_Z     256      //              256
#define T_H0    512      // [h*4+r]      512
#define T_D1    1024     //              512
#define T_D0    1536     //              512
#define T_RED   2048     // 2048 (A-C: [4][512]; D: [8][256])
#define T_S2P   4096     // [8 warps][4] 32
#define T_SG2   4128     // 8
#define T_NRM   4136     // 32
#define T_WYP   4168     // 32
#define T_FLAG  4200     // int
#define SMEM_FLOATS (OFF_TEAM + 2 * TEAM_STRIDE)
#define SMEM_BYTES  (SMEM_FLOATS * 4)

#define TBAR() asm volatile("bar.sync %0, 256;" :: "r"(team + 1) : "memory")

__global__ void __launch_bounds__(THREADS, 1)
blnn_main_kernel(const float* __restrict__ x_in,
                 const float* __restrict__ Wy0, const float* __restrict__ by0,
                 const float* __restrict__ Wy1, const float* __restrict__ by1,
                 const float* __restrict__ Wz1,
                 const float* __restrict__ Wy2, const float* __restrict__ by2,
                 const float* __restrict__ Wz2,
                 float* __restrict__ out)
{
    extern __shared__ float sm[];
    float* wz1t = sm + OFF_WZ1T;
    float* wy0t = sm + OFF_WY0T;
    float* wy1t = sm + OFF_WY1T;
    float* wy2v = sm + OFF_WY2V;
    float* wz2v = sm + OFF_WZ2V;
    float* by0v = sm + OFF_BY0V;
    float* by1v = sm + OFF_BY1V;
    float* misc = sm + OFF_MISC;

    const int tid   = threadIdx.x;
    const int l     = tid & 31;
    const int team  = tid >> 8;        // 0,1
    const int wt    = tid & 255;       // thread-in-team
    const int wteam = wt >> 5;         // warp-in-team 0..7
    // GEMV A/B/C mapping (4 chunks x 2 h-groups)
    const int g   = wteam & 1;
    const int ch  = wteam >> 1;        // 0..3
    const int hA  = g * 64 + l;
    const int hB  = hA + 32;
    // stage D mapping (8 chunks x 2 c/lane)
    const int cA  = l, cB = l + 32;
    // combine A/B/C mapping: (h, row-pair)
    const int hQ  = wt >> 1;
    const int prQ = wt & 1;
    // combine D mapping: (c, row)
    const int cD  = wt >> 2;
    const int rD  = wt & 3;

    float* tb   = sm + OFF_TEAM + team * TEAM_STRIDE;
    float* xT   = tb + T_X;
    float* zT   = tb + T_Z;
    float* h0T  = tb + T_H0;
    float* d1T  = tb + T_D1;
    float* d0T  = tb + T_D0;
    float* redT = tb + T_RED;
    float* s2pT = tb + T_S2P;
    float* sg2T = tb + T_SG2;
    float* nrmT = tb + T_NRM;
    float* wypT = tb + T_WYP;
    volatile int* flagT = (volatile int*)(tb + T_FLAG);

    // ---- one-time staging ----
    for (int i2 = tid; i2 < 128 * 128; i2 += THREADS) {
        int j = i2 >> 7, k = i2 & 127;
        wz1t[k * 129 + j] = fmaxf(Wz1[i2], 0.0f);
    }
    for (int i2 = tid; i2 < 64 * 128; i2 += THREADS) {
        int cc = i2 >> 7, h = i2 & 127;
        wy0t[cc * 129 + h] = Wy0[h * 64 + cc];
        wy1t[cc * 129 + h] = Wy1[h * 64 + cc];
    }
    if (tid < 64)  wy2v[tid] = Wy2[tid];
    if (tid < 128) {
        wz2v[tid] = fmaxf(Wz2[tid], 0.0f);
        by0v[tid] = by0[tid];
        by1v[tid] = by1[tid];
    }
    const int r0 = blockIdx.x * 8 + team * 4;
    zT[wt] = x_in[(r0 + rD) * 64 + cD];
    xT[wt] = 1.0f;
    if (wt == 0) { *flagT = 0; }
    if (tid == 0) misc[0] = by2[0];
    __syncthreads();

    const float by2v = misc[0];
    // per-row Wy2^T x held in conv-thread registers (threads wt<4)
    float wy2x_reg = 0.0f;
    if (wt < 4) {
        float s = 0.0f;
        for (int i2 = 0; i2 < 64; i2++) s += wy2v[i2];
        wy2x_reg = s;   // x = 1 initially
    }

    #pragma unroll 1
    for (int it = 0; it < MAX_IT; ++it) {
        // ---- conv part 1 (threads wt<4): reduce it-1 partials, post err ---
        if (wt < 4 && it > 0) {
            float nr = 0.0f, ws = 0.0f;
            #pragma unroll
            for (int w = 0; w < 8; w++) {
                nr += nrmT[w * 4 + wt];
                ws += wypT[w * 4 + wt];
            }
            wy2x_reg = ws;
            float s = sqrtf(nr);
            s += __shfl_xor_sync(0xFu, s, 1, 4);
            s += __shfl_xor_sync(0xFu, s, 2, 4);
            if (wt == 0)
                atomicAdd(&g_stat[it - 1],
                          (1ULL << CNT_SHIFT) +
                          (u64)((double)s * 4294967296.0));
        }

        // ===== stage A: A = Wy0 x ; S = Wy1 x  (4 c-chunks, 2 h/lane) ======
        u64 S0 = 0, S1 = 0, S2 = 0, S3 = 0;
        {
            u64 A0 = 0, A1 = 0, A2 = 0, A3 = 0;
            const float* p0 = wy0t + ch * 16 * 129;
            const float* p1 = wy1t + ch * 16 * 129;
            const float* px = xT + ch * 16 * 4;
            #pragma unroll 8
            for (int cc = 0; cc < 16; cc++) {
                u64 w0A = dup2(p0[cc * 129 + hA]);
                u64 w0B = dup2(p0[cc * 129 + hB]);
                u64 w1A = dup2(p1[cc * 129 + hA]);
                u64 w1B = dup2(p1[cc * 129 + hB]);
                ulonglong2 xv = *(const ulonglong2*)(px + cc * 4);
                A0 = fma2(w0A, xv.x, A0); A1 = fma2(w0A, xv.y, A1);
                A2 = fma2(w0B, xv.x, A2); A3 = fma2(w0B, xv.y, A3);
                S0 = fma2(w1A, xv.x, S0); S1 = fma2(w1A, xv.y, S1);
                S2 = fma2(w1B, xv.x, S2); S3 = fma2(w1B, xv.y, S3);
            }
            *(ulonglong2*)(redT + ch * 512 + hA * 4) = make_ulonglong2(A0, A1);
            *(ulonglong2*)(redT + ch * 512 + hB * 4) = make_ulonglong2(A2, A3);
        }
        TBAR();

        // ---- combine A (f32x2): h0 + sg0 (kept in regs) --------------------
        float sg0_0, sg0_1;
        {
            const float2* rp = (const float2*)redT;
            float2 a = rp[wt];
            #pragma unroll
            for (int p = 1; p < 4; p++) a = add2(a, rp[p * 256 + wt]);
            float bv = by0v[hQ];
            float h0x, h0y;
            act2(a.x + bv, h0x, sg0_0);
            act2(a.y + bv, h0y, sg0_1);
            ((float2*)h0T)[wt] = make_float2(h0x, h0y);
        }
        TBAR();

        // ===== stage B: S += Wz1c h0  (4 k-chunks, 2 h/lane) ===============
        {
            const float* pz = wz1t + ch * 32 * 129;
            const float* ph = h0T + ch * 32 * 4;
            #pragma unroll 8
            for (int kk = 0; kk < 32; kk++) {
                u64 wA = dup2(pz[kk * 129 + hA]);
                u64 wB = dup2(pz[kk * 129 + hB]);
                ulonglong2 hv = *(const ulonglong2*)(ph + kk * 4);
                S0 = fma2(wA, hv.x, S0); S1 = fma2(wA, hv.y, S1);
                S2 = fma2(wB, hv.x, S2); S3 = fma2(wB, hv.y, S3);
            }
            *(ulonglong2*)(redT + ch * 512 + hA * 4) = make_ulonglong2(S0, S1);
            *(ulonglong2*)(redT + ch * 512 + hB * 4) = make_ulonglong2(S2, S3);
        }
        TBAR();

        // ---- combine B (f32x2): d1' = wz2*sg1 (sg2 deferred); s2 partials -
        {
            const float2* rp = (const float2*)redT;
            float2 s = rp[wt];
            #pragma unroll
            for (int p = 1; p < 4; p++) s = add2(s, rp[p * 256 + wt]);
            float bv = by1v[hQ];
            float h1x, h1y, sg1x, sg1y;
            act2(s.x + bv, h1x, sg1x);
            act2(s.y + bv, h1y, sg1y);
            float wz2h = wz2v[hQ];
            ((float2*)d1T)[wt] = make_float2(wz2h * sg1x, wz2h * sg1y);
            float s2x = wz2h * h1x, s2y = wz2h * h1y;
            #pragma unroll
            for (int o = 2; o < 32; o <<= 1) {
                s2x += __shfl_xor_sync(0xffffffffu, s2x, o);
                s2y += __shfl_xor_sync(0xffffffffu, s2y, o);
            }
            if (l < 2)
                ((float2*)(s2pT + wteam * 4))[l] = make_float2(s2x, s2y);
        }
        TBAR();

        // ---- sg2 finalize (wt<4; overlaps stage C) ------------------------
        if (wt < 4) {
            float s2t = 0.0f;
            #pragma unroll
            for (int w = 0; w < 8; w++) s2t += s2pT[w * 4 + wt];
            float e = __expf(-(s2t + wy2x_reg + by2v));
            sg2T[wt] = __fdividef(1.0f, 1.0f + e);
        }

        // ===== stage C: Wz1c^T d1' (4 j-chunks, 2 h/lane) ==================
        {
            u64 C0 = 0, C1 = 0, C2 = 0, C3 = 0;
            const float* pzA = wz1t + hA * 129 + ch * 32;
            const float* pzB = wz1t + hB * 129 + ch * 32;
            const float* pd = d1T + ch * 32 * 4;
            #pragma unroll 8
            for (int jj = 0; jj < 32; jj++) {
                u64 wA = dup2(pzA[jj]);
                u64 wB = dup2(pzB[jj]);
                ulonglong2 dv = *(const ulonglong2*)(pd + jj * 4);
                C0 = fma2(wA, dv.x, C0); C1 = fma2(wA, dv.y, C1);
                C2 = fma2(wB, dv.x, C2); C3 = fma2(wB, dv.y, C3);
            }
            *(ulonglong2*)(redT + ch * 512 + hA * 4) = make_ulonglong2(C0, C1);
            *(ulonglong2*)(redT + ch * 512 + hB * 4) = make_ulonglong2(C2, C3);
        }
        TBAR();

        // ---- combine C (f32x2): d0' = sg0 * sum ---------------------------
        {
            const float2* rp = (const float2*)redT;
            float2 c2 = rp[wt];
            #pragma unroll
            for (int p = 1; p < 4; p++) c2 = add2(c2, rp[p * 256 + wt]);
            ((float2*)d0T)[wt] = make_float2(sg0_0 * c2.x, sg0_1 * c2.y);
        }
        TBAR();

        // ===== stage D: Wy1^T d1' + Wy0^T d0' (8 h-chunks, 2 c/lane) =======
        {
            u64 G0 = 0, G1 = 0, G2 = 0, G3 = 0;
            const int hb = wteam * 16;
            const float* p1A = wy1t + cA * 129 + hb;
            const float* p1B = wy1t + cB * 129 + hb;
            const float* p0A = wy0t + cA * 129 + hb;
            const float* p0B = wy0t + cB * 129 + hb;
            const float* q1 = d1T + hb * 4;
            const float* q0 = d0T + hb * 4;
            #pragma unroll 8
            for (int h2 = 0; h2 < 16; h2++) {
                u64 w1A = dup2(p1A[h2]);
                u64 w1B = dup2(p1B[h2]);
                u64 w0A = dup2(p0A[h2]);
                u64 w0B = dup2(p0B[h2]);
                ulonglong2 a = *(const ulonglong2*)(q1 + h2 * 4);
                ulonglong2 b = *(const ulonglong2*)(q0 + h2 * 4);
                G0 = fma2(w1A, a.x, G0); G1 = fma2(w1A, a.y, G1);
                G0 = fma2(w0A, b.x, G0); G1 = fma2(w0A, b.y, G1);
                G2 = fma2(w1B, a.x, G2); G3 = fma2(w1B, a.y, G3);
                G2 = fma2(w0B, b.x, G2); G3 = fma2(w0B, b.y, G3);
            }
            *(ulonglong2*)(redT + wteam * 256 + cA * 4) = make_ulonglong2(G0, G1);
            *(ulonglong2*)(redT + wteam * 256 + cB * 4) = make_ulonglong2(G2, G3);
        }

        // ---- conv part 2: spin + set flag (latest legal point) ------------
        if (wt == 0 && it > 0) {
            u64 vstat;
            do {
                asm volatile("ld.global.cg.u64 %0, [%1];"
                             : "=l"(vstat) : "l"(g_stat + (it - 1)));
            } while ((vstat >> CNT_SHIFT) < NUNITS);
            *flagT = (vstat & ERR_MASK) < ERR_THRESH;
        }
        TBAR();
        if (*flagT) break;   // update of it never ran -> xT is final

        // ---- combine D: residual + update + norm/wyp partials -------------
        {
            float gs = redT[wt];
            #pragma unroll
            for (int p = 1; p < 8; p++) gs += redT[p * 256 + wt];
            float sg2 = sg2T[rD];
            float wy2c = wy2v[cD];
            float xc = xT[wt];
            float gf = fmaf(sg2, gs + wy2c, xc);
            float rv = zT[wt] - gf;
            float nn = rv * rv;
            float lr = 2.0f / ((float)it + 1.0f);
            float xn = fmaf(lr, rv, xc);
            xT[wt] = xn;
            float p2 = wy2c * xn;
            #pragma unroll
            for (int o = 4; o < 32; o <<= 1) {
                nn += __shfl_xor_sync(0xffffffffu, nn, o);
                p2 += __shfl_xor_sync(0xffffffffu, p2, o);
            }
            if (l < 4) { nrmT[wteam * 4 + l] = nn; wypT[wteam * 4 + l] = p2; }
        }
        TBAR();
    }

    out[(r0 + rD) * 64 + cD] = xT[wt] + zT[wt];
}

extern "C" void kernel_launch(void* const* d_in, const int* in_sizes, int n_in,
                              void* d_out, int out_size) {
    const float* x   = (const float*)d_in[0];
    const float* Wy0 = (const float*)d_in[1];
    const float* by0 = (const float*)d_in[2];
    const float* Wy1 = (const float*)d_in[3];
    const float* by1 = (const float*)d_in[4];
    const float* Wz1 = (const float*)d_in[5];
    const float* Wy2 = (const float*)d_in[6];
    const float* by2 = (const float*)d_in[7];
    const float* Wz2 = (const float*)d_in[8];
    float* out = (float*)d_out;

    static bool attr_set = false;
    if (!attr_set) {
        cudaFuncSetAttribute(blnn_main_kernel,
                             cudaFuncAttributeMaxDynamicSharedMemorySize,
                             SMEM_BYTES);
        attr_set = true;
    }

    blnn_init_kernel<<<1, 512>>>();
    blnn_main_kernel<<<NCTA, THREADS, SMEM_BYTES>>>(x, Wy0, by0, Wy1, by1, Wz1,
                                                    Wy2, by2, Wz2, out);
}

// round 11
// speedup vs baseline: 1.0192x; 1.0192x over previous
#include <cuda_runtime.h>
#include <cstdint>

// ---------------------------------------------------------------------------
// BLNN round 11: R9 (single 16-warp team, weights at traffic floor) with the
//  convergence spin moved to the latest legal point (after stage-D GEMV,
//  before combine-D). err(it-1) is posted at loop top, so the global atomic
//  round-trip + cross-CTA spread now has ~4 segments (~1 iteration) of slack
//  instead of 1. Update is gated by the flag -> no rollback buffers.
// ---------------------------------------------------------------------------

#define NCTA      128
#define THREADS   512
#define NUNITS    128ULL
#define MAX_IT    500
#define CNT_SHIFT 52
#define ERR_MASK  ((1ULL << 52) - 1)
#define ERR_THRESH 4398046511ULL   // 0.001*1024*2^32

typedef unsigned long long u64;

__device__ u64 g_stat[MAX_IT];

__global__ void blnn_init_kernel() {
    int i = blockIdx.x * blockDim.x + threadIdx.x;
    if (i < MAX_IT) g_stat[i] = 0ULL;
}

__device__ __forceinline__ u64 dup2(float w) {
    u64 r; asm("mov.b64 %0,{%1,%1};" : "=l"(r) : "f"(w)); return r;
}
__device__ __forceinline__ u64 fma2(u64 a, u64 b, u64 c) {
    u64 d; asm("fma.rn.f32x2 %0,%1,%2,%3;" : "=l"(d) : "l"(a), "l"(b), "l"(c));
    return d;
}
__device__ __forceinline__ float2 add2(float2 a, float2 b) {
    return make_float2(a.x + b.x, a.y + b.y);
}
__device__ __forceinline__ void act2(float a, float& sp, float& sg) {
    float e = __expf(-fabsf(a));
    float u = 1.0f + e;
    float r = __fdividef(1.0f, u);
    sp = fmaxf(a, 0.0f) + __logf(u);
    sg = (a >= 0.0f) ? r : e * r;
}

// ---- shared layout (float offsets) ----
#define OFF_WZ1T  0
#define OFF_WY0T  16512
#define OFF_WY1T  24768
#define OFF_WY2V  33024
#define OFF_WZ2V  33088
#define OFF_BY0V  33216
#define OFF_BY1V  33344
#define OFF_XLO   33472
#define OFF_XHI   33728
#define OFF_ZLO   33984
#define OFF_ZHI   34240
#define OFF_H0LO  34496
#define OFF_H0HI  35008
#define OFF_D1LO  35520
#define OFF_D1HI  36032
#define OFF_D0LO  36544
#define OFF_D0HI  37056
#define OFF_RLO   37568   // 4096
#define OFF_RHI   41664   // 4096
#define OFF_S2PL  45760   // 32
#define OFF_S2PH  45792   // 32
#define OFF_SG2S  45824   // 8
#define OFF_NRMP  45832   // 32
#define OFF_WYP   45864   // 32
#define OFF_WY2X  45896   // 8
#define OFF_MISC  45904   // 8
#define SMEM_FLOATS 45912
#define SMEM_BYTES  (SMEM_FLOATS * 4)

__global__ void __launch_bounds__(THREADS, 1)
blnn_main_kernel(const float* __restrict__ x_in,
                 const float* __restrict__ Wy0, const float* __restrict__ by0,
                 const float* __restrict__ Wy1, const float* __restrict__ by1,
                 const float* __restrict__ Wz1,
                 const float* __restrict__ Wy2, const float* __restrict__ by2,
                 const float* __restrict__ Wz2,
                 float* __restrict__ out)
{
    extern __shared__ float sm[];
    float* wz1t = sm + OFF_WZ1T;
    float* wy0t = sm + OFF_WY0T;
    float* wy1t = sm + OFF_WY1T;
    float* wy2v = sm + OFF_WY2V;
    float* wz2v = sm + OFF_WZ2V;
    float* by0v = sm + OFF_BY0V;
    float* by1v = sm + OFF_BY1V;
    float* xLo  = sm + OFF_XLO;   float* xHi  = sm + OFF_XHI;
    float* zLo  = sm + OFF_ZLO;   float* zHi  = sm + OFF_ZHI;
    float* h0Lo = sm + OFF_H0LO;  float* h0Hi = sm + OFF_H0HI;
    float* d1Lo = sm + OFF_D1LO;  float* d1Hi = sm + OFF_D1HI;
    float* d0Lo = sm + OFF_D0LO;  float* d0Hi = sm + OFF_D0HI;
    float* rLo  = sm + OFF_RLO;   float* rHi  = sm + OFF_RHI;
    float* s2pL = sm + OFF_S2PL;  float* s2pH = sm + OFF_S2PH;
    float* sg2s = sm + OFF_SG2S;
    float* nrmp = sm + OFF_NRMP;  float* wyp  = sm + OFF_WYP;
    float* wy2x = sm + OFF_WY2X;  float* misc = sm + OFF_MISC;
    volatile int* flagI = (volatile int*)(misc + 1);

    const int tid  = threadIdx.x;
    const int l    = tid & 31;
    const int warp = tid >> 5;
    // GEMV A/B/C mapping
    const int g    = warp & 1;        // h-group
    const int ch   = warp >> 1;       // contraction chunk 0..7
    const int hA   = g * 64 + l;
    const int hB   = hA + 32;
    const int cA   = l, cB = l + 32;  // stage D owned c
    // combine A/B/C mapping: (half, h, rl-pair)
    const int half = tid >> 8;        // 0 Lo, 1 Hi
    const int idx  = tid & 255;       // = 2*h + pr
    const int hQ   = idx >> 1;
    const int prQ  = idx & 1;
    const int wl   = warp & 7;        // warp-in-half
    // combine D mapping (tid < 256): (halfD, c, pr)
    const int halfD = tid >> 7;
    const int idx2  = tid & 127;      // = 2*c + pr
    const int cQ    = idx2 >> 1;
    const int prD   = idx2 & 1;

    // ---- one-time staging ----
    for (int i2 = tid; i2 < 128 * 128; i2 += THREADS) {
        int j = i2 >> 7, k = i2 & 127;
        wz1t[k * 129 + j] = fmaxf(Wz1[i2], 0.0f);
    }
    for (int i2 = tid; i2 < 64 * 128; i2 += THREADS) {
        int cc = i2 >> 7, h = i2 & 127;
        wy0t[cc * 129 + h] = Wy0[h * 64 + cc];
        wy1t[cc * 129 + h] = Wy1[h * 64 + cc];
    }
    if (tid < 64)  wy2v[tid] = Wy2[tid];
    if (tid < 128) {
        wz2v[tid] = fmaxf(Wz2[tid], 0.0f);
        by0v[tid] = by0[tid];
        by1v[tid] = by1[tid];
    }
    const int r0 = blockIdx.x * 8;
    {   // x buffers [c*4 + rl]; rows 0-3 Lo, 4-7 Hi
        int cc = tid >> 3, rr = tid & 7;
        float zv = x_in[(r0 + rr) * 64 + cc];
        if (rr < 4) { zLo[cc * 4 + rr] = zv; xLo[cc * 4 + rr] = 1.0f; }
        else        { zHi[cc * 4 + rr - 4] = zv; xHi[cc * 4 + rr - 4] = 1.0f; }
    }
    if (tid == 0) { misc[0] = by2[0]; *flagI = 0; }
    __syncthreads();
    if (tid == 0) {
        float s = 0.0f;
        for (int i2 = 0; i2 < 64; i2++) s += wy2v[i2];
        #pragma unroll
        for (int r = 0; r < 8; r++) wy2x[r] = s;   // x = 1 initially
    }
    __syncthreads();

    const float by2v = misc[0];

    #pragma unroll 1
    for (int it = 0; it < MAX_IT; ++it) {
        // ---- conv part 1 (loop top): reduce it-1 partials, post err -------
        if (tid < 8 && it > 0) {
            int wb = (tid >> 2) * 4, rr = tid & 3;
            float nr = 0.0f, ws = 0.0f;
            #pragma unroll
            for (int w = 0; w < 4; w++) {
                nr += nrmp[(wb + w) * 4 + rr];
                ws += wyp[(wb + w) * 4 + rr];
            }
            wy2x[tid] = ws;
            float s = sqrtf(nr);
            s += __shfl_xor_sync(0xffu, s, 4, 8);
            s += __shfl_xor_sync(0xffu, s, 2, 8);
            s += __shfl_xor_sync(0xffu, s, 1, 8);
            if (tid == 0)
                atomicAdd(&g_stat[it - 1],
                          (1ULL << CNT_SHIFT) +
                          (u64)((double)s * 4294967296.0));
        }

        // ===== stage A: A = Wy0 x ; S = Wy1 x  (8-c chunks, 2 h/lane) ======
        u64 S0=0,S1=0,S2=0,S3=0,S4=0,S5=0,S6=0,S7=0;
        {
            u64 A0=0,A1=0,A2=0,A3=0,A4=0,A5=0,A6=0,A7=0;
            const float* p0 = wy0t + ch * 8 * 129;
            const float* p1 = wy1t + ch * 8 * 129;
            const float* pxl = xLo + ch * 8 * 4;
            const float* pxh = xHi + ch * 8 * 4;
            #pragma unroll
            for (int cc = 0; cc < 8; cc++) {
                u64 w0A = dup2(p0[cc * 129 + hA]);
                u64 w0B = dup2(p0[cc * 129 + hB]);
                u64 w1A = dup2(p1[cc * 129 + hA]);
                u64 w1B = dup2(p1[cc * 129 + hB]);
                ulonglong2 xl = *(const ulonglong2*)(pxl + cc * 4);
                ulonglong2 xh = *(const ulonglong2*)(pxh + cc * 4);
                A0=fma2(w0A,xl.x,A0); A1=fma2(w0A,xl.y,A1);
                A2=fma2(w0A,xh.x,A2); A3=fma2(w0A,xh.y,A3);
                A4=fma2(w0B,xl.x,A4); A5=fma2(w0B,xl.y,A5);
                A6=fma2(w0B,xh.x,A6); A7=fma2(w0B,xh.y,A7);
                S0=fma2(w1A,xl.x,S0); S1=fma2(w1A,xl.y,S1);
                S2=fma2(w1A,xh.x,S2); S3=fma2(w1A,xh.y,S3);
                S4=fma2(w1B,xl.x,S4); S5=fma2(w1B,xl.y,S5);
                S6=fma2(w1B,xh.x,S6); S7=fma2(w1B,xh.y,S7);
            }
            *(ulonglong2*)(rLo + ch * 512 + hA * 4) = make_ulonglong2(A0, A1);
            *(ulonglong2*)(rHi + ch * 512 + hA * 4) = make_ulonglong2(A2, A3);
            *(ulonglong2*)(rLo + ch * 512 + hB * 4) = make_ulonglong2(A4, A5);
            *(ulonglong2*)(rHi + ch * 512 + hB * 4) = make_ulonglong2(A6, A7);
        }
        __syncthreads();

        // ---- combine A (f32x2): h0 + sg0 (sg0 pair kept in regs) ----------
        float sg0_0, sg0_1;
        {
            const float2* rp = (const float2*)(half ? rHi : rLo);
            float2 a = rp[idx];
            #pragma unroll
            for (int p = 1; p < 8; p++) a = add2(a, rp[p * 256 + idx]);
            float bv = by0v[hQ];
            float h0x, h0y;
            act2(a.x + bv, h0x, sg0_0);
            act2(a.y + bv, h0y, sg0_1);
            ((float2*)(half ? h0Hi : h0Lo))[idx] = make_float2(h0x, h0y);
        }
        __syncthreads();

        // ===== stage B: S += Wz1c h0  (8-k chunks, 2 h/lane) ===============
        {
            const float* pz = wz1t + ch * 16 * 129;
            const float* phl = h0Lo + ch * 16 * 4;
            const float* phh = h0Hi + ch * 16 * 4;
            #pragma unroll 8
            for (int kk = 0; kk < 16; kk++) {
                u64 wA = dup2(pz[kk * 129 + hA]);
                u64 wB = dup2(pz[kk * 129 + hB]);
                ulonglong2 hl = *(const ulonglong2*)(phl + kk * 4);
                ulonglong2 hh2 = *(const ulonglong2*)(phh + kk * 4);
                S0=fma2(wA,hl.x,S0); S1=fma2(wA,hl.y,S1);
                S2=fma2(wA,hh2.x,S2); S3=fma2(wA,hh2.y,S3);
                S4=fma2(wB,hl.x,S4); S5=fma2(wB,hl.y,S5);
                S6=fma2(wB,hh2.x,S6); S7=fma2(wB,hh2.y,S7);
            }
        }
        *(ulonglong2*)(rLo + ch * 512 + hA * 4) = make_ulonglong2(S0, S1);
        *(ulonglong2*)(rHi + ch * 512 + hA * 4) = make_ulonglong2(S2, S3);
        *(ulonglong2*)(rLo + ch * 512 + hB * 4) = make_ulonglong2(S4, S5);
        *(ulonglong2*)(rHi + ch * 512 + hB * 4) = make_ulonglong2(S6, S7);
        __syncthreads();

        // ---- combine B (f32x2): d1' = wz2*sg1 (sg2 deferred); s2 partials -
        {
            const float2* rp = (const float2*)(half ? rHi : rLo);
            float2 s = rp[idx];
            #pragma unroll
            for (int p = 1; p < 8; p++) s = add2(s, rp[p * 256 + idx]);
            float bv = by1v[hQ];
            float h1x, h1y, sg1x, sg1y;
            act2(s.x + bv, h1x, sg1x);
            act2(s.y + bv, h1y, sg1y);
            float wz2h = wz2v[hQ];
            ((float2*)(half ? d1Hi : d1Lo))[idx] =
                make_float2(wz2h * sg1x, wz2h * sg1y);
            float s2x = wz2h * h1x, s2y = wz2h * h1y;
            #pragma unroll
            for (int o = 2; o < 32; o <<= 1) {
                s2x += __shfl_xor_sync(0xffffffffu, s2x, o);
                s2y += __shfl_xor_sync(0xffffffffu, s2y, o);
            }
            if (l < 2) {
                float* sp = half ? s2pH : s2pL;
                ((float2*)(sp + wl * 4))[prQ] = make_float2(s2x, s2y);
            }
        }
        __syncthreads();

        // ---- sg2 finalize (8 threads, overlaps stage C) -------------------
        if (tid < 8) {
            const float* sp = (tid & 4) ? s2pH : s2pL;
            int rr = tid & 3;
            float s2t = 0.0f;
            #pragma unroll
            for (int w = 0; w < 8; w++) s2t += sp[w * 4 + rr];
            float e = __expf(-(s2t + wy2x[tid] + by2v));
            sg2s[tid] = __fdividef(1.0f, 1.0f + e);
        }

        // ===== stage C: Wz1c^T d1' (8-j chunks, 2 k/lane) ==================
        {
            u64 C0=0,C1=0,C2=0,C3=0,C4=0,C5=0,C6=0,C7=0;
            const float* pzA = wz1t + hA * 129 + ch * 16;
            const float* pzB = wz1t + hB * 129 + ch * 16;
            const float* pdl = d1Lo + ch * 16 * 4;
            const float* pdh = d1Hi + ch * 16 * 4;
            #pragma unroll 8
            for (int jj = 0; jj < 16; jj++) {
                u64 wA = dup2(pzA[jj]);
                u64 wB = dup2(pzB[jj]);
                ulonglong2 dl = *(const ulonglong2*)(pdl + jj * 4);
                ulonglong2 dh = *(const ulonglong2*)(pdh + jj * 4);
                C0=fma2(wA,dl.x,C0); C1=fma2(wA,dl.y,C1);
                C2=fma2(wA,dh.x,C2); C3=fma2(wA,dh.y,C3);
                C4=fma2(wB,dl.x,C4); C5=fma2(wB,dl.y,C5);
                C6=fma2(wB,dh.x,C6); C7=fma2(wB,dh.y,C7);
            }
            *(ulonglong2*)(rLo + ch * 512 + hA * 4) = make_ulonglong2(C0, C1);
            *(ulonglong2*)(rHi + ch * 512 + hA * 4) = make_ulonglong2(C2, C3);
            *(ulonglong2*)(rLo + ch * 512 + hB * 4) = make_ulonglong2(C4, C5);
            *(ulonglong2*)(rHi + ch * 512 + hB * 4) = make_ulonglong2(C6, C7);
        }
        __syncthreads();

        // ---- combine C (f32x2): d0' = sg0 * sum ---------------------------
        {
            const float2* rp = (const float2*)(half ? rHi : rLo);
            float2 c2 = rp[idx];
            #pragma unroll
            for (int p = 1; p < 8; p++) c2 = add2(c2, rp[p * 256 + idx]);
            ((float2*)(half ? d0Hi : d0Lo))[idx] =
                make_float2(sg0_0 * c2.x, sg0_1 * c2.y);
        }
        __syncthreads();

        // ===== stage D: Wy1^T d1' + Wy0^T d0' (16 h-chunks, 2 c/lane) ======
        {
            u64 G0=0,G1=0,G2=0,G3=0,G4=0,G5=0,G6=0,G7=0;
            const float* p1A = wy1t + cA * 129 + warp * 8;
            const float* p1B = wy1t + cB * 129 + warp * 8;
            const float* p0A = wy0t + cA * 129 + warp * 8;
            const float* p0B = wy0t + cB * 129 + warp * 8;
            const float* q1l = d1Lo + warp * 8 * 4;
            const float* q1h = d1Hi + warp * 8 * 4;
            const float* q0l = d0Lo + warp * 8 * 4;
            const float* q0h = d0Hi + warp * 8 * 4;
            #pragma unroll
            for (int h2 = 0; h2 < 8; h2++) {
                u64 w1A = dup2(p1A[h2]);
                u64 w1B = dup2(p1B[h2]);
                u64 w0A = dup2(p0A[h2]);
                u64 w0B = dup2(p0B[h2]);
                ulonglong2 al = *(const ulonglong2*)(q1l + h2 * 4);
                ulonglong2 ah = *(const ulonglong2*)(q1h + h2 * 4);
                ulonglong2 bl = *(const ulonglong2*)(q0l + h2 * 4);
                ulonglong2 bh = *(const ulonglong2*)(q0h + h2 * 4);
                G0=fma2(w1A,al.x,G0); G1=fma2(w1A,al.y,G1);
                G2=fma2(w1A,ah.x,G2); G3=fma2(w1A,ah.y,G3);
                G0=fma2(w0A,bl.x,G0); G1=fma2(w0A,bl.y,G1);
                G2=fma2(w0A,bh.x,G2); G3=fma2(w0A,bh.y,G3);
                G4=fma2(w1B,al.x,G4); G5=fma2(w1B,al.y,G5);
                G6=fma2(w1B,ah.x,G6); G7=fma2(w1B,ah.y,G7);
                G4=fma2(w0B,bl.x,G4); G5=fma2(w0B,bl.y,G5);
                G6=fma2(w0B,bh.x,G6); G7=fma2(w0B,bh.y,G7);
            }
            *(ulonglong2*)(rLo + warp * 256 + cA * 4) = make_ulonglong2(G0, G1);
            *(ulonglong2*)(rHi + warp * 256 + cA * 4) = make_ulonglong2(G2, G3);
            *(ulonglong2*)(rLo + warp * 256 + cB * 4) = make_ulonglong2(G4, G5);
            *(ulonglong2*)(rHi + warp * 256 + cB * 4) = make_ulonglong2(G6, G7);
        }

        // ---- conv part 2 (latest legal point): spin + decide flag ---------
        if (tid == 0 && it > 0) {
            u64 vstat;
            do {
                asm volatile("ld.global.cg.u64 %0, [%1];"
                             : "=l"(vstat) : "l"(g_stat + (it - 1)));
            } while ((vstat >> CNT_SHIFT) < NUNITS);
            *flagI = (vstat & ERR_MASK) < ERR_THRESH;
        }
        __syncthreads();
        if (*flagI) break;   // update of it never ran -> xb is final

        // ---- combine D (256 threads, f32x2): residual + update + partials -
        if (tid < 256) {
            const float2* rp = (const float2*)(halfD ? rHi : rLo);
            float2 gs = rp[idx2];
            #pragma unroll
            for (int p = 1; p < 16; p++) gs = add2(gs, rp[p * 128 + idx2]);
            float* xX  = halfD ? xHi : xLo;
            const float* zX = halfD ? zHi : zLo;
            float2 sg2p = ((const float2*)sg2s)[halfD * 2 + prD];
            float wy2c = wy2v[cQ];
            float2 xc = ((const float2*)xX)[idx2];
            float2 zz = ((const float2*)zX)[idx2];
            float gfx = fmaf(sg2p.x, gs.x + wy2c, xc.x);
            float gfy = fmaf(sg2p.y, gs.y + wy2c, xc.y);
            float rvx = zz.x - gfx, rvy = zz.y - gfy;
            float nnx = rvx * rvx, nny = rvy * rvy;
            float lr = 2.0f / ((float)it + 1.0f);
            float xnx = fmaf(lr, rvx, xc.x), xny = fmaf(lr, rvy, xc.y);
            ((float2*)xX)[idx2]  = make_float2(xnx, xny);
            float p2x = wy2c * xnx, p2y = wy2c * xny;
            #pragma unroll
            for (int o = 2; o < 32; o <<= 1) {
                nnx += __shfl_xor_sync(0xffffffffu, nnx, o);
                nny += __shfl_xor_sync(0xffffffffu, nny, o);
                p2x += __shfl_xor_sync(0xffffffffu, p2x, o);
                p2y += __shfl_xor_sync(0xffffffffu, p2y, o);
            }
            if (l < 2) {
                ((float2*)(nrmp + warp * 4))[prD] = make_float2(nnx, nny);
                ((float2*)(wyp  + warp * 4))[prD] = make_float2(p2x, p2y);
            }
        }
        __syncthreads();
    }

    if (tid < 256) {
        const float* xX = halfD ? xHi : xLo;
        const float* zX = halfD ? zHi : zLo;
        int rbase = r0 + halfD * 4 + prD * 2;
        out[rbase * 64 + cQ]       = xX[idx2 * 2]     + zX[idx2 * 2];
        out[(rbase + 1) * 64 + cQ] = xX[idx2 * 2 + 1] + zX[idx2 * 2 + 1];
    }
}

extern "C" void kernel_launch(void* const* d_in, const int* in_sizes, int n_in,
                              void* d_out, int out_size) {
    const float* x   = (const float*)d_in[0];
    const float* Wy0 = (const float*)d_in[1];
    const float* by0 = (const float*)d_in[2];
    const float* Wy1 = (const float*)d_in[3];
    const float* by1 = (const float*)d_in[4];
    const float* Wz1 = (const float*)d_in[5];
    const float* Wy2 = (const float*)d_in[6];
    const float* by2 = (const float*)d_in[7];
    const float* Wz2 = (const float*)d_in[8];
    float* out = (float*)d_out;

    static bool attr_set = false;
    if (!attr_set) {
        cudaFuncSetAttribute(blnn_main_kernel,
                             cudaFuncAttributeMaxDynamicSharedMemorySize,
                             SMEM_BYTES);
        attr_set = true;
    }

    blnn_init_kernel<<<1, 512>>>();
    blnn_main_kernel<<<NCTA, THREADS, SMEM_BYTES>>>(x, Wy0, by0, Wy1, by1, Wz1,
                                                    Wy2, by2, Wz2, out);
}

// round 12
// speedup vs baseline: 1.4618x; 1.4343x over previous
#include <cuda_runtime.h>
#include <cstdint>

// ---------------------------------------------------------------------------
// BLNN round 12: R9 structure exactly (spin after stage A, break before
//  combine-A) + register-pressure fix: Wy1·x moved out of stage A into
//  stage B, so only 8 u64 accumulators (not 16) live across combine-A.
// ---------------------------------------------------------------------------

#define NCTA      128
#define THREADS   512
#define NUNITS    128ULL
#define MAX_IT    500
#define CNT_SHIFT 52
#define ERR_MASK  ((1ULL << 52) - 1)
#define ERR_THRESH 4398046511ULL   // 0.001*1024*2^32

typedef unsigned long long u64;

__device__ u64 g_stat[MAX_IT];

__global__ void blnn_init_kernel() {
    int i = blockIdx.x * blockDim.x + threadIdx.x;
    if (i < MAX_IT) g_stat[i] = 0ULL;
}

__device__ __forceinline__ u64 dup2(float w) {
    u64 r; asm("mov.b64 %0,{%1,%1};" : "=l"(r) : "f"(w)); return r;
}
__device__ __forceinline__ u64 fma2(u64 a, u64 b, u64 c) {
    u64 d; asm("fma.rn.f32x2 %0,%1,%2,%3;" : "=l"(d) : "l"(a), "l"(b), "l"(c));
    return d;
}
__device__ __forceinline__ float2 add2(float2 a, float2 b) {
    return make_float2(a.x + b.x, a.y + b.y);
}
__device__ __forceinline__ void act2(float a, float& sp, float& sg) {
    float e = __expf(-fabsf(a));
    float u = 1.0f + e;
    float r = __fdividef(1.0f, u);
    sp = fmaxf(a, 0.0f) + __logf(u);
    sg = (a >= 0.0f) ? r : e * r;
}

// ---- shared layout (float offsets) ----
#define OFF_WZ1T  0
#define OFF_WY0T  16512
#define OFF_WY1T  24768
#define OFF_WY2V  33024
#define OFF_WZ2V  33088
#define OFF_BY0V  33216
#define OFF_BY1V  33344
#define OFF_XLO   33472
#define OFF_XHI   33728
#define OFF_ZLO   33984
#define OFF_ZHI   34240
#define OFF_H0LO  34496
#define OFF_H0HI  35008
#define OFF_D1LO  35520
#define OFF_D1HI  36032
#define OFF_D0LO  36544
#define OFF_D0HI  37056
#define OFF_RLO   37568   // 4096
#define OFF_RHI   41664   // 4096
#define OFF_S2PL  45760   // 32
#define OFF_S2PH  45792   // 32
#define OFF_SG2S  45824   // 8
#define OFF_NRMP  45832   // 32
#define OFF_WYP   45864   // 32
#define OFF_WY2X  45896   // 8
#define OFF_MISC  45904   // 8
#define SMEM_FLOATS 45912
#define SMEM_BYTES  (SMEM_FLOATS * 4)

__global__ void __launch_bounds__(THREADS, 1)
blnn_main_kernel(const float* __restrict__ x_in,
                 const float* __restrict__ Wy0, const float* __restrict__ by0,
                 const float* __restrict__ Wy1, const float* __restrict__ by1,
                 const float* __restrict__ Wz1,
                 const float* __restrict__ Wy2, const float* __restrict__ by2,
                 const float* __restrict__ Wz2,
                 float* __restrict__ out)
{
    extern __shared__ float sm[];
    float* wz1t = sm + OFF_WZ1T;
    float* wy0t = sm + OFF_WY0T;
    float* wy1t = sm + OFF_WY1T;
    float* wy2v = sm + OFF_WY2V;
    float* wz2v = sm + OFF_WZ2V;
    float* by0v = sm + OFF_BY0V;
    float* by1v = sm + OFF_BY1V;
    float* xLo  = sm + OFF_XLO;   float* xHi  = sm + OFF_XHI;
    float* zLo  = sm + OFF_ZLO;   float* zHi  = sm + OFF_ZHI;
    float* h0Lo = sm + OFF_H0LO;  float* h0Hi = sm + OFF_H0HI;
    float* d1Lo = sm + OFF_D1LO;  float* d1Hi = sm + OFF_D1HI;
    float* d0Lo = sm + OFF_D0LO;  float* d0Hi = sm + OFF_D0HI;
    float* rLo  = sm + OFF_RLO;   float* rHi  = sm + OFF_RHI;
    float* s2pL = sm + OFF_S2PL;  float* s2pH = sm + OFF_S2PH;
    float* sg2s = sm + OFF_SG2S;
    float* nrmp = sm + OFF_NRMP;  float* wyp  = sm + OFF_WYP;
    float* wy2x = sm + OFF_WY2X;  float* misc = sm + OFF_MISC;
    volatile int* flagI = (volatile int*)(misc + 1);

    const int tid  = threadIdx.x;
    const int l    = tid & 31;
    const int warp = tid >> 5;
    // GEMV A/B/C mapping
    const int g    = warp & 1;        // h-group
    const int ch   = warp >> 1;       // contraction chunk 0..7
    const int hA   = g * 64 + l;
    const int hB   = hA + 32;
    const int cA   = l, cB = l + 32;  // stage D owned c
    // combine A/B/C mapping: (half, h, rl-pair)
    const int half = tid >> 8;        // 0 Lo, 1 Hi
    const int idx  = tid & 255;       // = 2*h + pr
    const int hQ   = idx >> 1;
    const int prQ  = idx & 1;
    const int wl   = warp & 7;        // warp-in-half
    // combine D mapping (tid < 256): (halfD, c, pr)
    const int halfD = tid >> 7;
    const int idx2  = tid & 127;      // = 2*c + pr
    const int cQ    = idx2 >> 1;
    const int prD   = idx2 & 1;

    // ---- one-time staging ----
    for (int i2 = tid; i2 < 128 * 128; i2 += THREADS) {
        int j = i2 >> 7, k = i2 & 127;
        wz1t[k * 129 + j] = fmaxf(Wz1[i2], 0.0f);
    }
    for (int i2 = tid; i2 < 64 * 128; i2 += THREADS) {
        int cc = i2 >> 7, h = i2 & 127;
        wy0t[cc * 129 + h] = Wy0[h * 64 + cc];
        wy1t[cc * 129 + h] = Wy1[h * 64 + cc];
    }
    if (tid < 64)  wy2v[tid] = Wy2[tid];
    if (tid < 128) {
        wz2v[tid] = fmaxf(Wz2[tid], 0.0f);
        by0v[tid] = by0[tid];
        by1v[tid] = by1[tid];
    }
    const int r0 = blockIdx.x * 8;
    {   // x buffers [c*4 + rl]; rows 0-3 Lo, 4-7 Hi
        int cc = tid >> 3, rr = tid & 7;
        float zv = x_in[(r0 + rr) * 64 + cc];
        if (rr < 4) { zLo[cc * 4 + rr] = zv; xLo[cc * 4 + rr] = 1.0f; }
        else        { zHi[cc * 4 + rr - 4] = zv; xHi[cc * 4 + rr - 4] = 1.0f; }
    }
    if (tid == 0) { misc[0] = by2[0]; *flagI = 0; }
    __syncthreads();
    if (tid == 0) {
        float s = 0.0f;
        for (int i2 = 0; i2 < 64; i2++) s += wy2v[i2];
        #pragma unroll
        for (int r = 0; r < 8; r++) wy2x[r] = s;   // x = 1 initially
    }
    __syncthreads();

    const float by2v = misc[0];

    #pragma unroll 1
    for (int it = 0; it < MAX_IT; ++it) {
        // ---- conv part 1 (loop top): reduce it-1 partials, post err -------
        if (tid < 8 && it > 0) {
            int wb = (tid >> 2) * 4, rr = tid & 3;
            float nr = 0.0f, ws = 0.0f;
            #pragma unroll
            for (int w = 0; w < 4; w++) {
                nr += nrmp[(wb + w) * 4 + rr];
                ws += wyp[(wb + w) * 4 + rr];
            }
            wy2x[tid] = ws;
            float s = sqrtf(nr);
            s += __shfl_xor_sync(0xffu, s, 4, 8);
            s += __shfl_xor_sync(0xffu, s, 2, 8);
            s += __shfl_xor_sync(0xffu, s, 1, 8);
            if (tid == 0)
                atomicAdd(&g_stat[it - 1],
                          (1ULL << CNT_SHIFT) +
                          (u64)((double)s * 4294967296.0));
        }

        // ===== stage A: A = Wy0 x  (8-c chunks, 2 h/lane) ==================
        {
            u64 A0=0,A1=0,A2=0,A3=0,A4=0,A5=0,A6=0,A7=0;
            const float* p0 = wy0t + ch * 8 * 129;
            const float* pxl = xLo + ch * 8 * 4;
            const float* pxh = xHi + ch * 8 * 4;
            #pragma unroll
            for (int cc = 0; cc < 8; cc++) {
                u64 w0A = dup2(p0[cc * 129 + hA]);
                u64 w0B = dup2(p0[cc * 129 + hB]);
                ulonglong2 xl = *(const ulonglong2*)(pxl + cc * 4);
                ulonglong2 xh = *(const ulonglong2*)(pxh + cc * 4);
                A0=fma2(w0A,xl.x,A0); A1=fma2(w0A,xl.y,A1);
                A2=fma2(w0A,xh.x,A2); A3=fma2(w0A,xh.y,A3);
                A4=fma2(w0B,xl.x,A4); A5=fma2(w0B,xl.y,A5);
                A6=fma2(w0B,xh.x,A6); A7=fma2(w0B,xh.y,A7);
            }
            *(ulonglong2*)(rLo + ch * 512 + hA * 4) = make_ulonglong2(A0, A1);
            *(ulonglong2*)(rHi + ch * 512 + hA * 4) = make_ulonglong2(A2, A3);
            *(ulonglong2*)(rLo + ch * 512 + hB * 4) = make_ulonglong2(A4, A5);
            *(ulonglong2*)(rHi + ch * 512 + hB * 4) = make_ulonglong2(A6, A7);
        }

        // ---- conv part 2 (after GEMV A): spin + decide flag ----------------
        if (tid == 0 && it > 0) {
            u64 vstat;
            do {
                asm volatile("ld.global.cg.u64 %0, [%1];"
                             : "=l"(vstat) : "l"(g_stat + (it - 1)));
            } while ((vstat >> CNT_SHIFT) < NUNITS);
            *flagI = (vstat & ERR_MASK) < ERR_THRESH;
        }
        __syncthreads();
        if (*flagI) break;   // update of it never ran -> xb is final

        // ---- combine A (f32x2): h0 + sg0 (sg0 pair kept in regs) ----------
        float sg0_0, sg0_1;
        {
            const float2* rp = (const float2*)(half ? rHi : rLo);
            float2 a = rp[idx];
            #pragma unroll
            for (int p = 1; p < 8; p++) a = add2(a, rp[p * 256 + idx]);
            float bv = by0v[hQ];
            float h0x, h0y;
            act2(a.x + bv, h0x, sg0_0);
            act2(a.y + bv, h0y, sg0_1);
            ((float2*)(half ? h0Hi : h0Lo))[idx] = make_float2(h0x, h0y);
        }
        __syncthreads();

        // ===== stage B: S = Wy1 x + Wz1c h0  (8 chunks, 2 h/lane) ==========
        u64 S0=0,S1=0,S2=0,S3=0,S4=0,S5=0,S6=0,S7=0;
        {
            const float* p1 = wy1t + ch * 8 * 129;
            const float* pxl = xLo + ch * 8 * 4;
            const float* pxh = xHi + ch * 8 * 4;
            #pragma unroll
            for (int cc = 0; cc < 8; cc++) {
                u64 w1A = dup2(p1[cc * 129 + hA]);
                u64 w1B = dup2(p1[cc * 129 + hB]);
                ulonglong2 xl = *(const ulonglong2*)(pxl + cc * 4);
                ulonglong2 xh = *(const ulonglong2*)(pxh + cc * 4);
                S0=fma2(w1A,xl.x,S0); S1=fma2(w1A,xl.y,S1);
                S2=fma2(w1A,xh.x,S2); S3=fma2(w1A,xh.y,S3);
                S4=fma2(w1B,xl.x,S4); S5=fma2(w1B,xl.y,S5);
                S6=fma2(w1B,xh.x,S6); S7=fma2(w1B,xh.y,S7);
            }
            const float* pz = wz1t + ch * 16 * 129;
            const float* phl = h0Lo + ch * 16 * 4;
            const float* phh = h0Hi + ch * 16 * 4;
            #pragma unroll 8
            for (int kk = 0; kk < 16; kk++) {
                u64 wA = dup2(pz[kk * 129 + hA]);
                u64 wB = dup2(pz[kk * 129 + hB]);
                ulonglong2 hl = *(const ulonglong2*)(phl + kk * 4);
                ulonglong2 hh2 = *(const ulonglong2*)(phh + kk * 4);
                S0=fma2(wA,hl.x,S0); S1=fma2(wA,hl.y,S1);
                S2=fma2(wA,hh2.x,S2); S3=fma2(wA,hh2.y,S3);
                S4=fma2(wB,hl.x,S4); S5=fma2(wB,hl.y,S5);
                S6=fma2(wB,hh2.x,S6); S7=fma2(wB,hh2.y,S7);
            }
        }
        *(ulonglong2*)(rLo + ch * 512 + hA * 4) = make_ulonglong2(S0, S1);
        *(ulonglong2*)(rHi + ch * 512 + hA * 4) = make_ulonglong2(S2, S3);
        *(ulonglong2*)(rLo + ch * 512 + hB * 4) = make_ulonglong2(S4, S5);
        *(ulonglong2*)(rHi + ch * 512 + hB * 4) = make_ulonglong2(S6, S7);
        __syncthreads();

        // ---- combine B (f32x2): d1' = wz2*sg1 (sg2 deferred); s2 partials -
        {
            const float2* rp = (const float2*)(half ? rHi : rLo);
            float2 s = rp[idx];
            #pragma unroll
            for (int p = 1; p < 8; p++) s = add2(s, rp[p * 256 + idx]);
            float bv = by1v[hQ];
            float h1x, h1y, sg1x, sg1y;
            act2(s.x + bv, h1x, sg1x);
            act2(s.y + bv, h1y, sg1y);
            float wz2h = wz2v[hQ];
            ((float2*)(half ? d1Hi : d1Lo))[idx] =
                make_float2(wz2h * sg1x, wz2h * sg1y);
            float s2x = wz2h * h1x, s2y = wz2h * h1y;
            #pragma unroll
            for (int o = 2; o < 32; o <<= 1) {
                s2x += __shfl_xor_sync(0xffffffffu, s2x, o);
                s2y += __shfl_xor_sync(0xffffffffu, s2y, o);
            }
            if (l < 2) {
                float* sp = half ? s2pH : s2pL;
                ((float2*)(sp + wl * 4))[prQ] = make_float2(s2x, s2y);
            }
        }
        __syncthreads();

        // ---- sg2 finalize (8 threads, overlaps stage C) -------------------
        if (tid < 8) {
            const float* sp = (tid & 4) ? s2pH : s2pL;
            int rr = tid & 3;
            float s2t = 0.0f;
            #pragma unroll
            for (int w = 0; w < 8; w++) s2t += sp[w * 4 + rr];
            float e = __expf(-(s2t + wy2x[tid] + by2v));
            sg2s[tid] = __fdividef(1.0f, 1.0f + e);
        }

        // ===== stage C: Wz1c^T d1' (8-j chunks, 2 k/lane) ==================
        {
            u64 C0=0,C1=0,C2=0,C3=0,C4=0,C5=0,C6=0,C7=0;
            const float* pzA = wz1t + hA * 129 + ch * 16;
            const float* pzB = wz1t + hB * 129 + ch * 16;
            const float* pdl = d1Lo + ch * 16 * 4;
            const float* pdh = d1Hi + ch * 16 * 4;
            #pragma unroll 8
            for (int jj = 0; jj < 16; jj++) {
                u64 wA = dup2(pzA[jj]);
                u64 wB = dup2(pzB[jj]);
                ulonglong2 dl = *(const ulonglong2*)(pdl + jj * 4);
                ulonglong2 dh = *(const ulonglong2*)(pdh + jj * 4);
                C0=fma2(wA,dl.x,C0); C1=fma2(wA,dl.y,C1);
                C2=fma2(wA,dh.x,C2); C3=fma2(wA,dh.y,C3);
                C4=fma2(wB,dl.x,C4); C5=fma2(wB,dl.y,C5);
                C6=fma2(wB,dh.x,C6); C7=fma2(wB,dh.y,C7);
            }
            *(ulonglong2*)(rLo + ch * 512 + hA * 4) = make_ulonglong2(C0, C1);
            *(ulonglong2*)(rHi + ch * 512 + hA * 4) = make_ulonglong2(C2, C3);
            *(ulonglong2*)(rLo + ch * 512 + hB * 4) = make_ulonglong2(C4, C5);
            *(ulonglong2*)(rHi + ch * 512 + hB * 4) = make_ulonglong2(C6, C7);
        }
        __syncthreads();

        // ---- combine C (f32x2): d0' = sg0 * sum ---------------------------
        {
            const float2* rp = (const float2*)(half ? rHi : rLo);
            float2 c2 = rp[idx];
            #pragma unroll
            for (int p = 1; p < 8; p++) c2 = add2(c2, rp[p * 256 + idx]);
            ((float2*)(half ? d0Hi : d0Lo))[idx] =
                make_float2(sg0_0 * c2.x, sg0_1 * c2.y);
        }
        __syncthreads();

        // ===== stage D: Wy1^T d1' + Wy0^T d0' (16 h-chunks, 2 c/lane) ======
        {
            u64 G0=0,G1=0,G2=0,G3=0,G4=0,G5=0,G6=0,G7=0;
            const float* p1A = wy1t + cA * 129 + warp * 8;
            const float* p1B = wy1t + cB * 129 + warp * 8;
            const float* p0A = wy0t + cA * 129 + warp * 8;
            const float* p0B = wy0t + cB * 129 + warp * 8;
            const float* q1l = d1Lo + warp * 8 * 4;
            const float* q1h = d1Hi + warp * 8 * 4;
            const float* q0l = d0Lo + warp * 8 * 4;
            const float* q0h = d0Hi + warp * 8 * 4;
            #pragma unroll
            for (int h2 = 0; h2 < 8; h2++) {
                u64 w1A = dup2(p1A[h2]);
                u64 w1B = dup2(p1B[h2]);
                u64 w0A = dup2(p0A[h2]);
                u64 w0B = dup2(p0B[h2]);
                ulonglong2 al = *(const ulonglong2*)(q1l + h2 * 4);
                ulonglong2 ah = *(const ulonglong2*)(q1h + h2 * 4);
                ulonglong2 bl = *(const ulonglong2*)(q0l + h2 * 4);
                ulonglong2 bh = *(const ulonglong2*)(q0h + h2 * 4);
                G0=fma2(w1A,al.x,G0); G1=fma2(w1A,al.y,G1);
                G2=fma2(w1A,ah.x,G2); G3=fma2(w1A,ah.y,G3);
                G0=fma2(w0A,bl.x,G0); G1=fma2(w0A,bl.y,G1);
                G2=fma2(w0A,bh.x,G2); G3=fma2(w0A,bh.y,G3);
                G4=fma2(w1B,al.x,G4); G5=fma2(w1B,al.y,G5);
                G6=fma2(w1B,ah.x,G6); G7=fma2(w1B,ah.y,G7);
                G4=fma2(w0B,bl.x,G4); G5=fma2(w0B,bl.y,G5);
                G6=fma2(w0B,bh.x,G6); G7=fma2(w0B,bh.y,G7);
            }
            *(ulonglong2*)(rLo + warp * 256 + cA * 4) = make_ulonglong2(G0, G1);
            *(ulonglong2*)(rHi + warp * 256 + cA * 4) = make_ulonglong2(G2, G3);
            *(ulonglong2*)(rLo + warp * 256 + cB * 4) = make_ulonglong2(G4, G5);
            *(ulonglong2*)(rHi + warp * 256 + cB * 4) = make_ulonglong2(G6, G7);
        }
        __syncthreads();

        // ---- combine D (256 threads, f32x2): residual + update + partials -
        if (tid < 256) {
            const float2* rp = (const float2*)(halfD ? rHi : rLo);
            float2 gs = rp[idx2];
            #pragma unroll
            for (int p = 1; p < 16; p++) gs = add2(gs, rp[p * 128 + idx2]);
            float* xX  = halfD ? xHi : xLo;
            const float* zX = halfD ? zHi : zLo;
            float2 sg2p = ((const float2*)sg2s)[halfD * 2 + prD];
            float wy2c = wy2v[cQ];
            float2 xc = ((const float2*)xX)[idx2];
            float2 zz = ((const float2*)zX)[idx2];
            float gfx = fmaf(sg2p.x, gs.x + wy2c, xc.x);
            float gfy = fmaf(sg2p.y, gs.y + wy2c, xc.y);
            float rvx = zz.x - gfx, rvy = zz.y - gfy;
            float nnx = rvx * rvx, nny = rvy * rvy;
            float lr = 2.0f / ((float)it + 1.0f);
            float xnx = fmaf(lr, rvx, xc.x), xny = fmaf(lr, rvy, xc.y);
            ((float2*)xX)[idx2]  = make_float2(xnx, xny);
            float p2x = wy2c * xnx, p2y = wy2c * xny;
            #pragma unroll
            for (int o = 2; o < 32; o <<= 1) {
                nnx += __shfl_xor_sync(0xffffffffu, nnx, o);
                nny += __shfl_xor_sync(0xffffffffu, nny, o);
                p2x += __shfl_xor_sync(0xffffffffu, p2x, o);
                p2y += __shfl_xor_sync(0xffffffffu, p2y, o);
            }
            if (l < 2) {
                ((float2*)(nrmp + warp * 4))[prD] = make_float2(nnx, nny);
                ((float2*)(wyp  + warp * 4))[prD] = make_float2(p2x, p2y);
            }
        }
        __syncthreads();
    }

    if (tid < 256) {
        const float* xX = halfD ? xHi : xLo;
        const float* zX = halfD ? zHi : zLo;
        int rbase = r0 + halfD * 4 + prD * 2;
        out[rbase * 64 + cQ]       = xX[idx2 * 2]     + zX[idx2 * 2];
        out[(rbase + 1) * 64 + cQ] = xX[idx2 * 2 + 1] + zX[idx2 * 2 + 1];
    }
}

extern "C" void kernel_launch(void* const* d_in, const int* in_sizes, int n_in,
                              void* d_out, int out_size) {
    const float* x   = (const float*)d_in[0];
    const float* Wy0 = (const float*)d_in[1];
    const float* by0 = (const float*)d_in[2];
    const float* Wy1 = (const float*)d_in[3];
    const float* by1 = (const float*)d_in[4];
    const float* Wz1 = (const float*)d_in[5];
    const float* Wy2 = (const float*)d_in[6];
    const float* by2 = (const float*)d_in[7];
    const float* Wz2 = (const float*)d_in[8];
    float* out = (float*)d_out;

    static bool attr_set = false;
    if (!attr_set) {
        cudaFuncSetAttribute(blnn_main_kernel,
                             cudaFuncAttributeMaxDynamicSharedMemorySize,
                             SMEM_BYTES);
        attr_set = true;
    }

    blnn_init_kernel<<<1, 512>>>();
    blnn_main_kernel<<<NCTA, THREADS, SMEM_BYTES>>>(x, Wy0, by0, Wy1, by1, Wz1,
                                                    Wy2, by2, Wz2, out);
}